// round 8
// baseline (speedup 1.0000x reference)
#include <cuda_runtime.h>
#include <math.h>
#include <stdint.h>

// ---------------- problem constants ----------------
#define BATCH_MAX 65536
#define DIMV 64
#define CTXD 384
#define HIDD 128
#define NPR 5
#define MEMN 10
#define EPSV 1e-8f
#define GRID_A 148

typedef unsigned long long u64;

__device__ __forceinline__ u64 pk2(float a) {
    u64 r; asm("mov.b64 %0,{%1,%1};" : "=l"(r) : "f"(a)); return r;
}
__device__ __forceinline__ void ffma2(u64& d, u64 a, u64 b) {
    asm("fma.rn.f32x2 %0,%1,%2,%0;" : "+l"(d) : "l"(a), "l"(b));
}
__device__ __forceinline__ float2 up2(u64 v) {
    float2 f; asm("mov.b64 {%0,%1},%2;" : "=f"(f.x), "=f"(f.y) : "l"(v)); return f;
}
__device__ __forceinline__ float tf32f(float x) {
    uint32_t u; asm("cvt.rna.tf32.f32 %0, %1;" : "=r"(u) : "f"(x));
    return __uint_as_float(u);
}
__device__ __forceinline__ void mma_tf32(float c[4], uint32_t a0, uint32_t a1,
                                         uint32_t a2, uint32_t a3,
                                         uint32_t b0, uint32_t b1) {
    asm volatile(
        "mma.sync.aligned.m16n8k8.row.col.f32.tf32.tf32.f32 "
        "{%0,%1,%2,%3},{%4,%5,%6,%7},{%8,%9},{%0,%1,%2,%3};"
        : "+f"(c[0]), "+f"(c[1]), "+f"(c[2]), "+f"(c[3])
        : "r"(a0), "r"(a1), "r"(a2), "r"(a3), "r"(b0), "r"(b1));
}

// ---------------- device scratch ----------------
__device__ float g_e[BATCH_MAX * DIMV];
__device__ float g_partials[GRID_A];
__device__ float g_stress;
__device__ float g_gic[2][192];
__device__ float g_M[NPR * CTXD];
__device__ float g_ibc[NPR];

// ================= kernel C0: M = ideal_w[:,64:] @ ctx_w, ibc ==============
extern "C" __global__ void
kC0(const float* __restrict__ ideal_w, const float* __restrict__ ctx_w,
    const float* __restrict__ ctx_b, const float* __restrict__ ideal_b)
{
    const int p = blockIdx.x;
    const int k = threadIdx.x;
    float s = 0.0f;
    #pragma unroll 8
    for (int d = 0; d < 64; d++)
        s = fmaf(ideal_w[p * 128 + 64 + d], ctx_w[d * 384 + k], s);
    g_M[p * 384 + k] = s;
    if (k == 0) {
        float c = ideal_b[p];
        for (int d = 0; d < 64; d++)
            c = fmaf(ideal_w[p * 128 + 64 + d], ctx_b[d], c);
        g_ibc[p] = c;
    }
}

// ================= kernel A2 (unchanged fp32 path) =========================
#define A2_W1   0
#define A2_W2   8192
#define A2_IWT  16384
#define A2_M    16704
#define A2_PE   18624
#define A2_B1   18944
#define A2_B2   19072
#define A2_IBC  19136
#define A2_PI   19144
#define A2_TH   19208
#define A2_H1   27912
#define A2_LG   44808
#define A2_RED  45832
#define A2_TOT  46344
#define SMEM_A2 (A2_TOT * 4)

extern "C" __global__ void __launch_bounds__(512)
kA2(const float* __restrict__ theta, const float* __restrict__ context,
    const float* __restrict__ emo_w1, const float* __restrict__ emo_b1,
    const float* __restrict__ emo_w2, const float* __restrict__ emo_b2,
    const float* __restrict__ prime_embeds, const float* __restrict__ ideal_w,
    const float* __restrict__ prev_ideal,
    const float* __restrict__ freq_w, const float* __restrict__ freq_b,
    float* __restrict__ out_res, float* __restrict__ out_om,
    float* __restrict__ out_pw, int ntiles)
{
    extern __shared__ float sm[];
    const int t = threadIdx.x;

    for (int i = t; i < HIDD * 64; i += 512) {
        int j = i / 64, d = i % 64;
        sm[A2_W1 + d * 128 + j] = emo_w1[i];
    }
    for (int i = t; i < 64 * HIDD; i += 512) {
        int d = i / 128, j = i % 128;
        sm[A2_W2 + j * 64 + d] = emo_w2[i];
    }
    for (int i = t; i < NPR * 64; i += 512)
        sm[A2_IWT + i] = ideal_w[(i / 64) * 128 + (i % 64)];
    for (int i = t; i < NPR * CTXD; i += 512) sm[A2_M + i] = g_M[i];
    for (int i = t; i < NPR * 64;  i += 512) sm[A2_PE + i] = prime_embeds[i];
    if (t < 128) sm[A2_B1 + t] = emo_b1[t];
    if (t < 64)  sm[A2_B2 + t] = emo_b2[t];
    if (t < NPR) sm[A2_IBC + t] = g_ibc[t];
    if (t < 64)  sm[A2_PI + t] = prev_ideal[t];
    __syncthreads();

    const float fw = freq_w[0], fb = freq_b[0];
    const int rb = t >> 4, jq = t & 15;
    const int r0 = rb * 4;
    const int lane = t & 31, wp = t >> 5;
    float st_acc = 0.0f;

    for (int tile = blockIdx.x; tile < ntiles; tile += gridDim.x) {
        __syncthreads();
        const int row0 = tile * 128;
        {
            const float4* th4 = (const float4*)(theta + (size_t)row0 * DIMV);
            for (int i = t; i < 128 * 16; i += 512) {
                int r = i / 16, c = i % 16;
                ((float4*)(sm + A2_TH + r * 68))[c] = th4[i];
            }
        }
        __syncthreads();

        {
            ulonglong2 b1a = *(const ulonglong2*)(sm + A2_B1 + jq * 4);
            ulonglong2 b1b = *(const ulonglong2*)(sm + A2_B1 + 64 + jq * 4);
            u64 a1[4][2], a2[4][2];
            #pragma unroll
            for (int m = 0; m < 4; m++) {
                a1[m][0] = b1a.x; a1[m][1] = b1a.y;
                a2[m][0] = b1b.x; a2[m][1] = b1b.y;
            }
            #pragma unroll 1
            for (int k4 = 0; k4 < DIMV; k4 += 4) {
                float4 xv[4];
                #pragma unroll
                for (int m = 0; m < 4; m++)
                    xv[m] = *(const float4*)(sm + A2_TH + (r0 + m) * 68 + k4);
                #pragma unroll
                for (int kk = 0; kk < 4; kk++) {
                    int k = k4 + kk;
                    ulonglong2 w1 = *(const ulonglong2*)(sm + A2_W1 + k * 128 + jq * 4);
                    ulonglong2 w2 = *(const ulonglong2*)(sm + A2_W1 + k * 128 + 64 + jq * 4);
                    #pragma unroll
                    for (int m = 0; m < 4; m++) {
                        float xs = (kk == 0) ? xv[m].x : (kk == 1) ? xv[m].y : (kk == 2) ? xv[m].z : xv[m].w;
                        u64 xx = pk2(xs);
                        ffma2(a1[m][0], xx, w1.x); ffma2(a1[m][1], xx, w1.y);
                        ffma2(a2[m][0], xx, w2.x); ffma2(a2[m][1], xx, w2.y);
                    }
                }
            }
            #pragma unroll
            for (int m = 0; m < 4; m++) {
                float* h1 = sm + A2_H1 + (r0 + m) * 132;
                float2 v0 = up2(a1[m][0]), v1 = up2(a1[m][1]);
                float2 v2 = up2(a2[m][0]), v3 = up2(a2[m][1]);
                h1[jq * 4 + 0] = tanhf(v0.x); h1[jq * 4 + 1] = tanhf(v0.y);
                h1[jq * 4 + 2] = tanhf(v1.x); h1[jq * 4 + 3] = tanhf(v1.y);
                h1[64 + jq * 4 + 0] = tanhf(v2.x); h1[64 + jq * 4 + 1] = tanhf(v2.y);
                h1[64 + jq * 4 + 2] = tanhf(v3.x); h1[64 + jq * 4 + 3] = tanhf(v3.y);
            }
        }

        for (int rr = 0; rr < 8; rr++) {
            const int row = wp * 8 + rr;
            const float* crow = context + (size_t)(row0 + row) * CTXD;
            float p0 = 0, p1 = 0, p2 = 0, p3 = 0, p4 = 0;
            #pragma unroll
            for (int ch = 0; ch < 12; ch++) {
                int k = lane + 32 * ch;
                float c = __ldg(crow + k);
                p0 = fmaf(c, sm[A2_M + 0 * 384 + k], p0);
                p1 = fmaf(c, sm[A2_M + 1 * 384 + k], p1);
                p2 = fmaf(c, sm[A2_M + 2 * 384 + k], p2);
                p3 = fmaf(c, sm[A2_M + 3 * 384 + k], p3);
                p4 = fmaf(c, sm[A2_M + 4 * 384 + k], p4);
            }
            #pragma unroll
            for (int ch = 0; ch < 2; ch++) {
                int k = lane + 32 * ch;
                float tv = sm[A2_TH + row * 68 + k];
                p0 = fmaf(tv, sm[A2_IWT + 0 * 64 + k], p0);
                p1 = fmaf(tv, sm[A2_IWT + 1 * 64 + k], p1);
                p2 = fmaf(tv, sm[A2_IWT + 2 * 64 + k], p2);
                p3 = fmaf(tv, sm[A2_IWT + 3 * 64 + k], p3);
                p4 = fmaf(tv, sm[A2_IWT + 4 * 64 + k], p4);
            }
            #pragma unroll
            for (int o = 16; o > 0; o >>= 1) {
                p0 += __shfl_xor_sync(0xffffffffu, p0, o);
                p1 += __shfl_xor_sync(0xffffffffu, p1, o);
                p2 += __shfl_xor_sync(0xffffffffu, p2, o);
                p3 += __shfl_xor_sync(0xffffffffu, p3, o);
                p4 += __shfl_xor_sync(0xffffffffu, p4, o);
            }
            if (lane == 0) {
                sm[A2_LG + row * 8 + 0] = p0 + sm[A2_IBC + 0];
                sm[A2_LG + row * 8 + 1] = p1 + sm[A2_IBC + 1];
                sm[A2_LG + row * 8 + 2] = p2 + sm[A2_IBC + 2];
                sm[A2_LG + row * 8 + 3] = p3 + sm[A2_IBC + 3];
                sm[A2_LG + row * 8 + 4] = p4 + sm[A2_IBC + 4];
            }
        }
        __syncthreads();

        {
            ulonglong2 b2q = *(const ulonglong2*)(sm + A2_B2 + jq * 4);
            u64 ea[4][2];
            #pragma unroll
            for (int m = 0; m < 4; m++) { ea[m][0] = b2q.x; ea[m][1] = b2q.y; }
            #pragma unroll 1
            for (int k4 = 0; k4 < HIDD; k4 += 4) {
                float4 xv[4];
                #pragma unroll
                for (int m = 0; m < 4; m++)
                    xv[m] = *(const float4*)(sm + A2_H1 + (r0 + m) * 132 + k4);
                #pragma unroll
                for (int kk = 0; kk < 4; kk++) {
                    int k = k4 + kk;
                    ulonglong2 w = *(const ulonglong2*)(sm + A2_W2 + k * 64 + jq * 4);
                    #pragma unroll
                    for (int m = 0; m < 4; m++) {
                        float xs = (kk == 0) ? xv[m].x : (kk == 1) ? xv[m].y : (kk == 2) ? xv[m].z : xv[m].w;
                        u64 xx = pk2(xs);
                        ffma2(ea[m][0], xx, w.x); ffma2(ea[m][1], xx, w.y);
                    }
                }
            }
            #pragma unroll
            for (int m = 0; m < 4; m++) {
                float2 v0 = up2(ea[m][0]), v1 = up2(ea[m][1]);
                float4 ev;
                ev.x = fmaxf(v0.x, 0.f); ev.y = fmaxf(v0.y, 0.f);
                ev.z = fmaxf(v1.x, 0.f); ev.w = fmaxf(v1.y, 0.f);
                *(float4*)(g_e + (size_t)(row0 + r0 + m) * DIMV + jq * 4) = ev;
            }
        }

        float pi4[4];
        { float4 p = *(const float4*)(sm + A2_PI + jq * 4); pi4[0]=p.x; pi4[1]=p.y; pi4[2]=p.z; pi4[3]=p.w; }
        #pragma unroll
        for (int m = 0; m < 4; m++) {
            const int row = r0 + m;
            float l[NPR], mx = -1e30f, pw[NPR];
            #pragma unroll
            for (int p = 0; p < NPR; p++) { l[p] = sm[A2_LG + row * 8 + p]; mx = fmaxf(mx, l[p]); }
            float s = 0.f;
            #pragma unroll
            for (int p = 0; p < NPR; p++) { pw[p] = expf(l[p] - mx); s += pw[p]; }
            float inv = 1.0f / s;
            #pragma unroll
            for (int p = 0; p < NPR; p++) pw[p] *= inv;
            if (jq < NPR) out_pw[(size_t)(row0 + row) * NPR + jq] = pw[jq];

            float4 thq = *(const float4*)(sm + A2_TH + row * 68 + jq * 4);
            float tv[4] = { thq.x, thq.y, thq.z, thq.w };
            float th2 = 0, ti2 = 0, dot = 0, st = 0, fr = 0;
            #pragma unroll
            for (int e = 0; e < 4; e++) {
                int d = jq * 4 + e;
                float iv = 0.f;
                #pragma unroll
                for (int p = 0; p < NPR; p++) iv = fmaf(pw[p], sm[A2_PE + p * 64 + d], iv);
                th2 = fmaf(tv[e], tv[e], th2);
                ti2 = fmaf(iv, iv, ti2);
                dot = fmaf(tv[e], iv, dot);
                float dd = tv[e] - iv; st = fmaf(dd, dd, st);
                float df = iv - pi4[e]; fr = fmaf(df, df, fr);
            }
            st_acc += st;
            #pragma unroll
            for (int o = 1; o < 16; o <<= 1) {
                th2 += __shfl_xor_sync(0xffffffffu, th2, o);
                ti2 += __shfl_xor_sync(0xffffffffu, ti2, o);
                dot += __shfl_xor_sync(0xffffffffu, dot, o);
                fr  += __shfl_xor_sync(0xffffffffu, fr,  o);
            }
            if (jq == 0) {
                float na = sqrtf(th2), nb = sqrtf(ti2);
                float t1 = dot / ((na + EPSV) * (nb + EPSV));
                float den = fmaxf((na / (na + EPSV)) * (nb / (nb + EPSV)), EPSV);
                out_res[row0 + row] = t1 / den;
                float fq = sqrtf(fr);
                out_om[row0 + row] = tanhf(fmaf(fq, fw, fb)) * (1.0f + 0.1f * sinf(fq));
            }
        }
    }

    __syncthreads();
    sm[A2_RED + t] = st_acc;
    __syncthreads();
    for (int o = 256; o > 0; o >>= 1) {
        if (t < o) sm[A2_RED + t] += sm[A2_RED + t + o];
        __syncthreads();
    }
    if (t == 0) g_partials[blockIdx.x] = sm[A2_RED];
}

// ================= kernel C: stress, o_vec, folded gi constants ============
extern "C" __global__ void
kC(const float* __restrict__ tw, const float* __restrict__ memory,
   const float* __restrict__ ipw, const float* __restrict__ ipb,
   const float* __restrict__ outw, const float* __restrict__ outb,
   const float* __restrict__ wih_f, const float* __restrict__ bih_f,
   const float* __restrict__ wih_r, const float* __restrict__ bih_r)
{
    __shared__ float attn[MEMN], mt[DIMV], vv[DIMV], ov[DIMV], stress_s;
    const int t = threadIdx.x;
    if (t == 0) {
        float m = -1e30f;
        for (int i = 0; i < MEMN; i++) m = fmaxf(m, tw[i]);
        float s = 0, ex[MEMN];
        for (int i = 0; i < MEMN; i++) { ex[i] = expf(tw[i] - m); s += ex[i]; }
        for (int i = 0; i < MEMN; i++) attn[i] = ex[i] / s;
        float acc = 0;
        for (int i = 0; i < GRID_A; i++) acc += g_partials[i];
        g_stress = acc; stress_s = acc;
    }
    __syncthreads();
    if (t < DIMV) {
        float s = 0;
        for (int m = 0; m < MEMN; m++) s = fmaf(attn[m], memory[m * DIMV + t], s);
        mt[t] = s;
    }
    __syncthreads();
    if (t < DIMV) {
        float s = ipb[2 * DIMV + t];
        for (int d = 0; d < DIMV; d++) s = fmaf(mt[d], ipw[(2 * DIMV + t) * DIMV + d], s);
        vv[t] = s;
    }
    __syncthreads();
    if (t < DIMV) {
        float s = outb[t];
        for (int i = 0; i < DIMV; i++) s = fmaf(vv[i], outw[t * DIMV + i], s);
        ov[t] = s;
    }
    __syncthreads();
    if (t < 192) {
        float sc = 0.001f * stress_s;
        float gf = bih_f[t], gr = bih_r[t];
        for (int k = 0; k < DIMV; k++) {
            gf = fmaf(ov[k], wih_f[t * 130 + k], gf);
            gr = fmaf(ov[k], wih_r[t * 130 + k], gr);
        }
        float sf = 0, sr = 0;
        for (int k = 64; k < 128; k++) { sf += wih_f[t * 130 + k]; sr += wih_r[t * 130 + k]; }
        g_gic[0][t] = fmaf(sc, sf, gf);
        g_gic[1][t] = fmaf(sc, sr, gr);
    }
}

// ================= kernel B: GRU via mma.sync tf32 ========================
// W: [256 cols][140] tf32, k-permuted per 8-block; X: [128 rows][140] tf32.
// Column grouping: jg*128 + gate*32 + jl, gates {r, z, i_n, h_n}.
#define BW_S  0                         // W: 256*140
#define BX_S  35840                     // X: 128*140
#define BB_S  53760                     // biases: 4*64
#define B_TOTF 54016
#define SMEM_B (B_TOTF * 4)
#define WSTR 140

extern "C" __global__ void __launch_bounds__(512)
kB(const float* __restrict__ wih_f, const float* __restrict__ whh_f,
   const float* __restrict__ bhh_f,
   const float* __restrict__ wih_r, const float* __restrict__ whh_r,
   const float* __restrict__ bhh_r,
   const float* __restrict__ hprev, const float* __restrict__ theta,
   const float* __restrict__ res_in, const float* __restrict__ om_in,
   float* __restrict__ hout, float* __restrict__ thout,
   float* __restrict__ eout, int ntiles, int Btot)
{
    extern __shared__ float sm[];
    const int t = threadIdx.x;
    const int dir = blockIdx.x & 1;

    const float* wih = dir ? wih_r : wih_f;
    const float* whh = dir ? whh_r : whh_f;
    const float* bhh = dir ? bhh_r : bhh_f;
    const float* hp  = hprev + (size_t)dir * Btot * DIMV;
    float* ho        = hout  + (size_t)dir * Btot * DIMV;

    // ---- stage W (tf32, j-major, k-pair permuted) ----
    for (int i = t; i < 256 * WSTR; i += 512) {
        int g = i / WSTR, scc = i % WSTR;
        int jg = g >> 7, gate = (g >> 5) & 3, jl = g & 31;
        int j = jg * 32 + jl;
        float val = 0.f;
        if (scc < 136) {
            int o = scc & 7;
            int pos = (o >> 1) + ((o & 1) << 2);
            int k = (scc & ~7) + pos;
            if (gate == 0) {
                if (k < 66) val = wih[j * 130 + 64 + k];
                else if (k < 130) val = whh[j * 64 + (k - 66)];
            } else if (gate == 1) {
                if (k < 66) val = wih[(64 + j) * 130 + 64 + k];
                else if (k < 130) val = whh[(64 + j) * 64 + (k - 66)];
            } else if (gate == 2) {
                if (k < 66) val = wih[(128 + j) * 130 + 64 + k];
            } else {
                if (k >= 66 && k < 130) val = whh[(128 + j) * 64 + (k - 66)];
            }
        }
        sm[BW_S + g * WSTR + scc] = tf32f(val);
    }
    // ---- biases ----
    if (t < 64) {
        sm[BB_S + t]       = g_gic[dir][t]       + bhh[t];        // r
        sm[BB_S + 64 + t]  = g_gic[dir][64 + t]  + bhh[64 + t];   // z
        sm[BB_S + 128 + t] = g_gic[dir][128 + t];                 // i_n
        sm[BB_S + 192 + t] = bhh[128 + t];                        // h_n
    }
    __syncthreads();

    const float sc = 0.001f * g_stress;
    const int lane = t & 31, wid = t >> 5;
    const int rowblk = wid >> 1;          // 0..7 : rows rowblk*16..+15
    const int jg = wid & 1;               // 0..1 : j 0..31 / 32..63
    const float lam = 0.7f, oml = 0.3f;
    const int nblk = gridDim.x >> 1;

    const float* aBase = sm + BX_S + (rowblk * 16 + (lane >> 2)) * WSTR + 2 * (lane & 3);
    const float* bBase = sm + BW_S + (jg * 128 + (lane >> 2)) * WSTR + 2 * (lane & 3);
    const float* bR  = sm + BB_S;
    const float* bZ  = sm + BB_S + 64;
    const float* bNx = sm + BB_S + 128;
    const float* bNh = sm + BB_S + 192;

    for (int tile = blockIdx.x >> 1; tile < ntiles; tile += nblk) {
        __syncthreads();
        const int row0 = tile * 128;

        // ---- stage X (tf32, k-pair permuted): [e | res | om | h | 0pad] ----
        for (int i = t; i < 128 * WSTR; i += 512) {
            int row = i / WSTR, scc = i % WSTR;
            float val = 0.f;
            if (scc < 136) {
                int o = scc & 7;
                int pos = (o >> 1) + ((o & 1) << 2);
                int k = (scc & ~7) + pos;
                int gr = row0 + row;
                if (k < 64) val = g_e[(size_t)gr * 64 + k];
                else if (k == 64) val = res_in[gr];
                else if (k == 65) val = om_in[gr];
                else if (k < 130) val = hp[(size_t)gr * 64 + (k - 66)];
            }
            sm[BX_S + row * WSTR + scc] = tf32f(val);
        }
        // e_theta output (dir 0 only): e + 0.001*stress
        if (dir == 0) {
            const float4* e4 = (const float4*)(g_e + (size_t)row0 * DIMV);
            float4* o4 = (float4*)(eout + (size_t)row0 * DIMV);
            for (int i = t; i < 128 * 16; i += 512) {
                float4 v = e4[i];
                v.x += sc; v.y += sc; v.z += sc; v.w += sc;
                o4[i] = v;
            }
        }
        __syncthreads();

        // ---- K loop: 17 k-blocks of 8, 16 j-tiles per warp ----
        float acc[16][4];
        #pragma unroll
        for (int tt = 0; tt < 16; tt++)
            { acc[tt][0] = 0.f; acc[tt][1] = 0.f; acc[tt][2] = 0.f; acc[tt][3] = 0.f; }

        const float* aPtr = aBase;
        const float* bPtr = bBase;
        #pragma unroll 1
        for (int b = 0; b < 17; b++) {
            uint2 aLo = *(const uint2*)(aPtr);              // a0, a2
            uint2 aHi = *(const uint2*)(aPtr + 8 * WSTR);   // a1, a3
            #pragma unroll
            for (int tt = 0; tt < 16; tt++) {
                uint2 bb = *(const uint2*)(bPtr + tt * 8 * WSTR);
                mma_tf32(acc[tt], aLo.x, aHi.x, aLo.y, aHi.y, bb.x, bb.y);
            }
            aPtr += 8; bPtr += 8;
        }

        __syncthreads();   // all MMAs done before h overwrites X cols 0..63

        // ---- epilogue: gates -> h, write into X cols 0..63 (own rows) ----
        #pragma unroll
        for (int rr = 0; rr < 2; rr++) {
            const int row = rowblk * 16 + (lane >> 2) + rr * 8;
            #pragma unroll
            for (int tt = 0; tt < 4; tt++) {
                #pragma unroll
                for (int e = 0; e < 2; e++) {
                    const int j = jg * 32 + tt * 8 + 2 * (lane & 3) + e;
                    const int ci = rr * 2 + e;
                    float vR = acc[tt][ci]      + bR[j];
                    float vZ = acc[4 + tt][ci]  + bZ[j];
                    float vN = acc[8 + tt][ci]  + bNx[j];
                    float vH = acc[12 + tt][ci] + bNh[j];
                    float rg = 1.0f / (1.0f + expf(-vR));
                    float zg = 1.0f / (1.0f + expf(-vZ));
                    float ng = tanhf(fmaf(rg, vH, vN));
                    int p = 66 + j;
                    int hcol = (p & ~7) + 2 * (p & 3) + ((p & 4) >> 2);
                    float hpv = sm[BX_S + row * WSTR + hcol];
                    sm[BX_S + row * WSTR + j] = fmaf(zg, hpv - ng, ng);
                }
            }
        }
        __syncthreads();

        // ---- write-out ----
        for (int i = t; i < 128 * 16; i += 512) {
            int row = i >> 4, q = i & 15;
            float4 hv = *(const float4*)(sm + BX_S + row * WSTR + q * 4);
            const size_t ob = (size_t)(row0 + row) * DIMV + q * 4;
            *(float4*)(ho + ob) = hv;
            if (dir == 0) {
                float4 th = *(const float4*)(theta + ob);
                float4 tn;
                tn.x = fmaf(lam, hv.x, oml * th.x); tn.y = fmaf(lam, hv.y, oml * th.y);
                tn.z = fmaf(lam, hv.z, oml * th.z); tn.w = fmaf(lam, hv.w, oml * th.w);
                *(float4*)(thout + ob) = tn;
            }
        }
    }
}

// ================= launch =================
extern "C" void kernel_launch(void* const* d_in, const int* in_sizes, int n_in,
                              void* d_out, int out_size)
{
    const float* theta     = (const float*)d_in[0];
    const float* context   = (const float*)d_in[1];
    const float* h_prev    = (const float*)d_in[2];
    const float* memory    = (const float*)d_in[3];
    const float* tw        = (const float*)d_in[4];
    const float* ipw       = (const float*)d_in[5];
    const float* ipb       = (const float*)d_in[6];
    const float* outw      = (const float*)d_in[7];
    const float* outb      = (const float*)d_in[8];
    const float* emo_w1    = (const float*)d_in[9];
    const float* emo_b1    = (const float*)d_in[10];
    const float* emo_w2    = (const float*)d_in[11];
    const float* emo_b2    = (const float*)d_in[12];
    const float* prime_emb = (const float*)d_in[13];
    const float* ctx_w     = (const float*)d_in[14];
    const float* ctx_b     = (const float*)d_in[15];
    const float* ideal_w   = (const float*)d_in[16];
    const float* ideal_b   = (const float*)d_in[17];
    const float* wih_f     = (const float*)d_in[18];
    const float* whh_f     = (const float*)d_in[19];
    const float* bih_f     = (const float*)d_in[20];
    const float* bhh_f     = (const float*)d_in[21];
    const float* wih_r     = (const float*)d_in[22];
    const float* whh_r     = (const float*)d_in[23];
    const float* bih_r     = (const float*)d_in[24];
    const float* bhh_r     = (const float*)d_in[25];
    const float* freq_w    = (const float*)d_in[26];
    const float* freq_b    = (const float*)d_in[27];
    const float* prev_id   = (const float*)d_in[28];

    const int B = in_sizes[0] / DIMV;
    const int ntiles = B / 128;

    float* out = (float*)d_out;
    float* o_thn = out;
    float* o_h   = out + (size_t)B * DIMV;
    float* o_e   = out + (size_t)3 * B * DIMV;
    float* o_res = out + (size_t)4 * B * DIMV;
    float* o_om  = o_res + B;
    float* o_pw  = o_om + B;

    cudaFuncSetAttribute((const void*)kA2, cudaFuncAttributeMaxDynamicSharedMemorySize, SMEM_A2);
    cudaFuncSetAttribute((const void*)kB,  cudaFuncAttributeMaxDynamicSharedMemorySize, SMEM_B);

    kC0<<<NPR, CTXD>>>(ideal_w, ctx_w, ctx_b, ideal_b);
    kA2<<<GRID_A, 512, SMEM_A2>>>(theta, context, emo_w1, emo_b1, emo_w2, emo_b2,
                                  prime_emb, ideal_w, prev_id,
                                  freq_w, freq_b, o_res, o_om, o_pw, ntiles);
    kC<<<1, 192>>>(tw, memory, ipw, ipb, outw, outb, wih_f, bih_f, wih_r, bih_r);
    kB<<<296, 512, SMEM_B>>>(wih_f, whh_f, bhh_f, wih_r, whh_r, bhh_r,
                             h_prev, theta, o_res, o_om,
                             o_h, o_thn, o_e, ntiles, B);
}

// round 16
// speedup vs baseline: 1.5138x; 1.5138x over previous
#include <cuda_runtime.h>
#include <cuda_fp16.h>
#include <math.h>
#include <stdint.h>

// ---------------- problem constants ----------------
#define BATCH_MAX 65536
#define DIMV 64
#define CTXD 384
#define HIDD 128
#define NPR 5
#define MEMN 10
#define EPSV 1e-8f
#define GRID_A 148

typedef unsigned long long u64;

__device__ __forceinline__ u64 pk2(float a) {
    u64 r; asm("mov.b64 %0,{%1,%1};" : "=l"(r) : "f"(a)); return r;
}
__device__ __forceinline__ void ffma2(u64& d, u64 a, u64 b) {
    asm("fma.rn.f32x2 %0,%1,%2,%0;" : "+l"(d) : "l"(a), "l"(b));
}
__device__ __forceinline__ float2 up2(u64 v) {
    float2 f; asm("mov.b64 {%0,%1},%2;" : "=f"(f.x), "=f"(f.y) : "l"(v)); return f;
}
__device__ __forceinline__ uint32_t smem_u32(const void* p) {
    uint32_t a;
    asm("{ .reg .u64 t; cvta.to.shared.u64 t, %1; cvt.u32.u64 %0, t; }" : "=r"(a) : "l"(p));
    return a;
}
__device__ __forceinline__ void ldmatrix_x4(uint32_t& r0, uint32_t& r1,
                                            uint32_t& r2, uint32_t& r3, uint32_t addr) {
    asm volatile("ldmatrix.sync.aligned.m8n8.x4.shared.b16 {%0,%1,%2,%3}, [%4];"
                 : "=r"(r0), "=r"(r1), "=r"(r2), "=r"(r3) : "r"(addr));
}
__device__ __forceinline__ void mma_f16(float c[4], uint32_t a0, uint32_t a1,
                                        uint32_t a2, uint32_t a3,
                                        uint32_t b0, uint32_t b1) {
    asm volatile(
        "mma.sync.aligned.m16n8k16.row.col.f32.f16.f16.f32 "
        "{%0,%1,%2,%3},{%4,%5,%6,%7},{%8,%9},{%0,%1,%2,%3};"
        : "+f"(c[0]), "+f"(c[1]), "+f"(c[2]), "+f"(c[3])
        : "r"(a0), "r"(a1), "r"(a2), "r"(a3), "r"(b0), "r"(b1));
}

// ---------------- device scratch ----------------
__device__ float g_e[BATCH_MAX * DIMV];
__device__ float g_partials[GRID_A];
__device__ float g_stress;
__device__ float g_gic[2][192];
__device__ float g_M[NPR * CTXD];
__device__ float g_ibc[NPR];

// ================= kernel C0 ==============
extern "C" __global__ void
kC0(const float* __restrict__ ideal_w, const float* __restrict__ ctx_w,
    const float* __restrict__ ctx_b, const float* __restrict__ ideal_b)
{
    const int p = blockIdx.x;
    const int k = threadIdx.x;
    float s = 0.0f;
    #pragma unroll 8
    for (int d = 0; d < 64; d++)
        s = fmaf(ideal_w[p * 128 + 64 + d], ctx_w[d * 384 + k], s);
    g_M[p * 384 + k] = s;
    if (k == 0) {
        float c = ideal_b[p];
        for (int d = 0; d < 64; d++)
            c = fmaf(ideal_w[p * 128 + 64 + d], ctx_b[d], c);
        g_ibc[p] = c;
    }
}

// ================= kernel A2 (unchanged fp32 FFMA2 path) ===================
#define A2_W1   0
#define A2_W2   8192
#define A2_IWT  16384
#define A2_M    16704
#define A2_PE   18624
#define A2_B1   18944
#define A2_B2   19072
#define A2_IBC  19136
#define A2_PI   19144
#define A2_TH   19208
#define A2_H1   27912
#define A2_LG   44808
#define A2_RED  45832
#define A2_TOT  46344
#define SMEM_A2 (A2_TOT * 4)

extern "C" __global__ void __launch_bounds__(512)
kA2(const float* __restrict__ theta, const float* __restrict__ context,
    const float* __restrict__ emo_w1, const float* __restrict__ emo_b1,
    const float* __restrict__ emo_w2, const float* __restrict__ emo_b2,
    const float* __restrict__ prime_embeds, const float* __restrict__ ideal_w,
    const float* __restrict__ prev_ideal,
    const float* __restrict__ freq_w, const float* __restrict__ freq_b,
    float* __restrict__ out_res, float* __restrict__ out_om,
    float* __restrict__ out_pw, int ntiles)
{
    extern __shared__ float sm[];
    const int t = threadIdx.x;

    for (int i = t; i < HIDD * 64; i += 512) {
        int j = i / 64, d = i % 64;
        sm[A2_W1 + d * 128 + j] = emo_w1[i];
    }
    for (int i = t; i < 64 * HIDD; i += 512) {
        int d = i / 128, j = i % 128;
        sm[A2_W2 + j * 64 + d] = emo_w2[i];
    }
    for (int i = t; i < NPR * 64; i += 512)
        sm[A2_IWT + i] = ideal_w[(i / 64) * 128 + (i % 64)];
    for (int i = t; i < NPR * CTXD; i += 512) sm[A2_M + i] = g_M[i];
    for (int i = t; i < NPR * 64;  i += 512) sm[A2_PE + i] = prime_embeds[i];
    if (t < 128) sm[A2_B1 + t] = emo_b1[t];
    if (t < 64)  sm[A2_B2 + t] = emo_b2[t];
    if (t < NPR) sm[A2_IBC + t] = g_ibc[t];
    if (t < 64)  sm[A2_PI + t] = prev_ideal[t];
    __syncthreads();

    const float fw = freq_w[0], fb = freq_b[0];
    const int rb = t >> 4, jq = t & 15;
    const int r0 = rb * 4;
    const int lane = t & 31, wp = t >> 5;
    float st_acc = 0.0f;

    for (int tile = blockIdx.x; tile < ntiles; tile += gridDim.x) {
        __syncthreads();
        const int row0 = tile * 128;
        {
            const float4* th4 = (const float4*)(theta + (size_t)row0 * DIMV);
            for (int i = t; i < 128 * 16; i += 512) {
                int r = i / 16, c = i % 16;
                ((float4*)(sm + A2_TH + r * 68))[c] = th4[i];
            }
        }
        __syncthreads();

        {
            ulonglong2 b1a = *(const ulonglong2*)(sm + A2_B1 + jq * 4);
            ulonglong2 b1b = *(const ulonglong2*)(sm + A2_B1 + 64 + jq * 4);
            u64 a1[4][2], a2[4][2];
            #pragma unroll
            for (int m = 0; m < 4; m++) {
                a1[m][0] = b1a.x; a1[m][1] = b1a.y;
                a2[m][0] = b1b.x; a2[m][1] = b1b.y;
            }
            #pragma unroll 1
            for (int k4 = 0; k4 < DIMV; k4 += 4) {
                float4 xv[4];
                #pragma unroll
                for (int m = 0; m < 4; m++)
                    xv[m] = *(const float4*)(sm + A2_TH + (r0 + m) * 68 + k4);
                #pragma unroll
                for (int kk = 0; kk < 4; kk++) {
                    int k = k4 + kk;
                    ulonglong2 w1 = *(const ulonglong2*)(sm + A2_W1 + k * 128 + jq * 4);
                    ulonglong2 w2 = *(const ulonglong2*)(sm + A2_W1 + k * 128 + 64 + jq * 4);
                    #pragma unroll
                    for (int m = 0; m < 4; m++) {
                        float xs = (kk == 0) ? xv[m].x : (kk == 1) ? xv[m].y : (kk == 2) ? xv[m].z : xv[m].w;
                        u64 xx = pk2(xs);
                        ffma2(a1[m][0], xx, w1.x); ffma2(a1[m][1], xx, w1.y);
                        ffma2(a2[m][0], xx, w2.x); ffma2(a2[m][1], xx, w2.y);
                    }
                }
            }
            #pragma unroll
            for (int m = 0; m < 4; m++) {
                float* h1 = sm + A2_H1 + (r0 + m) * 132;
                float2 v0 = up2(a1[m][0]), v1 = up2(a1[m][1]);
                float2 v2 = up2(a2[m][0]), v3 = up2(a2[m][1]);
                h1[jq * 4 + 0] = tanhf(v0.x); h1[jq * 4 + 1] = tanhf(v0.y);
                h1[jq * 4 + 2] = tanhf(v1.x); h1[jq * 4 + 3] = tanhf(v1.y);
                h1[64 + jq * 4 + 0] = tanhf(v2.x); h1[64 + jq * 4 + 1] = tanhf(v2.y);
                h1[64 + jq * 4 + 2] = tanhf(v3.x); h1[64 + jq * 4 + 3] = tanhf(v3.y);
            }
        }

        for (int rr = 0; rr < 8; rr++) {
            const int row = wp * 8 + rr;
            const float* crow = context + (size_t)(row0 + row) * CTXD;
            float p0 = 0, p1 = 0, p2 = 0, p3 = 0, p4 = 0;
            #pragma unroll
            for (int ch = 0; ch < 12; ch++) {
                int k = lane + 32 * ch;
                float c = __ldg(crow + k);
                p0 = fmaf(c, sm[A2_M + 0 * 384 + k], p0);
                p1 = fmaf(c, sm[A2_M + 1 * 384 + k], p1);
                p2 = fmaf(c, sm[A2_M + 2 * 384 + k], p2);
                p3 = fmaf(c, sm[A2_M + 3 * 384 + k], p3);
                p4 = fmaf(c, sm[A2_M + 4 * 384 + k], p4);
            }
            #pragma unroll
            for (int ch = 0; ch < 2; ch++) {
                int k = lane + 32 * ch;
                float tv = sm[A2_TH + row * 68 + k];
                p0 = fmaf(tv, sm[A2_IWT + 0 * 64 + k], p0);
                p1 = fmaf(tv, sm[A2_IWT + 1 * 64 + k], p1);
                p2 = fmaf(tv, sm[A2_IWT + 2 * 64 + k], p2);
                p3 = fmaf(tv, sm[A2_IWT + 3 * 64 + k], p3);
                p4 = fmaf(tv, sm[A2_IWT + 4 * 64 + k], p4);
            }
            #pragma unroll
            for (int o = 16; o > 0; o >>= 1) {
                p0 += __shfl_xor_sync(0xffffffffu, p0, o);
                p1 += __shfl_xor_sync(0xffffffffu, p1, o);
                p2 += __shfl_xor_sync(0xffffffffu, p2, o);
                p3 += __shfl_xor_sync(0xffffffffu, p3, o);
                p4 += __shfl_xor_sync(0xffffffffu, p4, o);
            }
            if (lane == 0) {
                sm[A2_LG + row * 8 + 0] = p0 + sm[A2_IBC + 0];
                sm[A2_LG + row * 8 + 1] = p1 + sm[A2_IBC + 1];
                sm[A2_LG + row * 8 + 2] = p2 + sm[A2_IBC + 2];
                sm[A2_LG + row * 8 + 3] = p3 + sm[A2_IBC + 3];
                sm[A2_LG + row * 8 + 4] = p4 + sm[A2_IBC + 4];
            }
        }
        __syncthreads();

        {
            ulonglong2 b2q = *(const ulonglong2*)(sm + A2_B2 + jq * 4);
            u64 ea[4][2];
            #pragma unroll
            for (int m = 0; m < 4; m++) { ea[m][0] = b2q.x; ea[m][1] = b2q.y; }
            #pragma unroll 1
            for (int k4 = 0; k4 < HIDD; k4 += 4) {
                float4 xv[4];
                #pragma unroll
                for (int m = 0; m < 4; m++)
                    xv[m] = *(const float4*)(sm + A2_H1 + (r0 + m) * 132 + k4);
                #pragma unroll
                for (int kk = 0; kk < 4; kk++) {
                    int k = k4 + kk;
                    ulonglong2 w = *(const ulonglong2*)(sm + A2_W2 + k * 64 + jq * 4);
                    #pragma unroll
                    for (int m = 0; m < 4; m++) {
                        float xs = (kk == 0) ? xv[m].x : (kk == 1) ? xv[m].y : (kk == 2) ? xv[m].z : xv[m].w;
                        u64 xx = pk2(xs);
                        ffma2(ea[m][0], xx, w.x); ffma2(ea[m][1], xx, w.y);
                    }
                }
            }
            #pragma unroll
            for (int m = 0; m < 4; m++) {
                float2 v0 = up2(ea[m][0]), v1 = up2(ea[m][1]);
                float4 ev;
                ev.x = fmaxf(v0.x, 0.f); ev.y = fmaxf(v0.y, 0.f);
                ev.z = fmaxf(v1.x, 0.f); ev.w = fmaxf(v1.y, 0.f);
                *(float4*)(g_e + (size_t)(row0 + r0 + m) * DIMV + jq * 4) = ev;
            }
        }

        float pi4[4];
        { float4 p = *(const float4*)(sm + A2_PI + jq * 4); pi4[0]=p.x; pi4[1]=p.y; pi4[2]=p.z; pi4[3]=p.w; }
        #pragma unroll
        for (int m = 0; m < 4; m++) {
            const int row = r0 + m;
            float l[NPR], mx = -1e30f, pw[NPR];
            #pragma unroll
            for (int p = 0; p < NPR; p++) { l[p] = sm[A2_LG + row * 8 + p]; mx = fmaxf(mx, l[p]); }
            float s = 0.f;
            #pragma unroll
            for (int p = 0; p < NPR; p++) { pw[p] = expf(l[p] - mx); s += pw[p]; }
            float inv = 1.0f / s;
            #pragma unroll
            for (int p = 0; p < NPR; p++) pw[p] *= inv;
            if (jq < NPR) out_pw[(size_t)(row0 + row) * NPR + jq] = pw[jq];

            float4 thq = *(const float4*)(sm + A2_TH + row * 68 + jq * 4);
            float tv[4] = { thq.x, thq.y, thq.z, thq.w };
            float th2 = 0, ti2 = 0, dot = 0, st = 0, fr = 0;
            #pragma unroll
            for (int e = 0; e < 4; e++) {
                int d = jq * 4 + e;
                float iv = 0.f;
                #pragma unroll
                for (int p = 0; p < NPR; p++) iv = fmaf(pw[p], sm[A2_PE + p * 64 + d], iv);
                th2 = fmaf(tv[e], tv[e], th2);
                ti2 = fmaf(iv, iv, ti2);
                dot = fmaf(tv[e], iv, dot);
                float dd = tv[e] - iv; st = fmaf(dd, dd, st);
                float df = iv - pi4[e]; fr = fmaf(df, df, fr);
            }
            st_acc += st;
            #pragma unroll
            for (int o = 1; o < 16; o <<= 1) {
                th2 += __shfl_xor_sync(0xffffffffu, th2, o);
                ti2 += __shfl_xor_sync(0xffffffffu, ti2, o);
                dot += __shfl_xor_sync(0xffffffffu, dot, o);
                fr  += __shfl_xor_sync(0xffffffffu, fr,  o);
            }
            if (jq == 0) {
                float na = sqrtf(th2), nb = sqrtf(ti2);
                float t1 = dot / ((na + EPSV) * (nb + EPSV));
                float den = fmaxf((na / (na + EPSV)) * (nb / (nb + EPSV)), EPSV);
                out_res[row0 + row] = t1 / den;
                float fq = sqrtf(fr);
                out_om[row0 + row] = tanhf(fmaf(fq, fw, fb)) * (1.0f + 0.1f * sinf(fq));
            }
        }
    }

    __syncthreads();
    sm[A2_RED + t] = st_acc;
    __syncthreads();
    for (int o = 256; o > 0; o >>= 1) {
        if (t < o) sm[A2_RED + t] += sm[A2_RED + t + o];
        __syncthreads();
    }
    if (t == 0) g_partials[blockIdx.x] = sm[A2_RED];
}

// ================= kernel C ============
extern "C" __global__ void
kC(const float* __restrict__ tw, const float* __restrict__ memory,
   const float* __restrict__ ipw, const float* __restrict__ ipb,
   const float* __restrict__ outw, const float* __restrict__ outb,
   const float* __restrict__ wih_f, const float* __restrict__ bih_f,
   const float* __restrict__ wih_r, const float* __restrict__ bih_r)
{
    __shared__ float attn[MEMN], mt[DIMV], vv[DIMV], ov[DIMV], stress_s;
    const int t = threadIdx.x;
    if (t == 0) {
        float m = -1e30f;
        for (int i = 0; i < MEMN; i++) m = fmaxf(m, tw[i]);
        float s = 0, ex[MEMN];
        for (int i = 0; i < MEMN; i++) { ex[i] = expf(tw[i] - m); s += ex[i]; }
        for (int i = 0; i < MEMN; i++) attn[i] = ex[i] / s;
        float acc = 0;
        for (int i = 0; i < GRID_A; i++) acc += g_partials[i];
        g_stress = acc; stress_s = acc;
    }
    __syncthreads();
    if (t < DIMV) {
        float s = 0;
        for (int m = 0; m < MEMN; m++) s = fmaf(attn[m], memory[m * DIMV + t], s);
        mt[t] = s;
    }
    __syncthreads();
    if (t < DIMV) {
        float s = ipb[2 * DIMV + t];
        for (int d = 0; d < DIMV; d++) s = fmaf(mt[d], ipw[(2 * DIMV + t) * DIMV + d], s);
        vv[t] = s;
    }
    __syncthreads();
    if (t < DIMV) {
        float s = outb[t];
        for (int i = 0; i < DIMV; i++) s = fmaf(vv[i], outw[t * DIMV + i], s);
        ov[t] = s;
    }
    __syncthreads();
    if (t < 192) {
        float sc = 0.001f * stress_s;
        float gf = bih_f[t], gr = bih_r[t];
        for (int k = 0; k < DIMV; k++) {
            gf = fmaf(ov[k], wih_f[t * 130 + k], gf);
            gr = fmaf(ov[k], wih_r[t * 130 + k], gr);
        }
        float sf = 0, sr = 0;
        for (int k = 64; k < 128; k++) { sf += wih_f[t * 130 + k]; sr += wih_r[t * 130 + k]; }
        g_gic[0][t] = fmaf(sc, sf, gf);
        g_gic[1][t] = fmaf(sc, sr, gr);
    }
}

// ================= kernel B: GRU via fp16 mma.sync m16n8k16 ================
// A: [128 m][144 k] half, stride 152 halfs (304B; 304%128=48 -> 8 rows hit 8
//    distinct 16B bank windows, conflict-free ldmatrix)
// B: [256 n][144 k] half, stride 152 halfs (304B)  <-- FIX: was 136 halfs,
//    which overflowed rows (144 k written/read per row) and corrupted weights
//   n = cg*64 + gate*16 + jl ; j = cg*16 + jl ; gates {r, z, i_n, h_n}
// K: 0..63 e ; 64 res ; 65 om ; 66..129 h_prev ; 130..143 zero
#define KB_A_OFF   0                    // bytes, size 128*304 = 38912
#define KB_B_OFF   38912                // bytes, size 256*304 = 77824 -> ends 116736
#define KB_HB_F    29184                // float idx (byte 116736), 128*68 floats -> ends 151552
#define KB_BI_F    37888                // float idx (byte 151552), 256 floats
#define SMEM_KB    152576
#define ASTR_B     304                  // A row stride bytes
#define BSTR_B     304                  // B row stride bytes
#define BSTR_H     152                  // B row stride halfs

extern "C" __global__ void __launch_bounds__(512)
kB(const float* __restrict__ wih_f, const float* __restrict__ whh_f,
   const float* __restrict__ bhh_f,
   const float* __restrict__ wih_r, const float* __restrict__ whh_r,
   const float* __restrict__ bhh_r,
   const float* __restrict__ hprev, const float* __restrict__ theta,
   const float* __restrict__ res_in, const float* __restrict__ om_in,
   float* __restrict__ hout, float* __restrict__ thout,
   float* __restrict__ eout, int ntiles, int Btot)
{
    extern __shared__ float smf[];
    __half* smh = (__half*)smf;
    const uint32_t smem_base = smem_u32(smf);
    const int t = threadIdx.x;
    const int dir = blockIdx.x & 1;

    const float* wih = dir ? wih_r : wih_f;
    const float* whh = dir ? whh_r : whh_f;
    const float* bhh = dir ? bhh_r : bhh_f;
    const float* hp  = hprev + (size_t)dir * Btot * DIMV;
    float* ho        = hout  + (size_t)dir * Btot * DIMV;

    // ---- stage B weights [n][k] fp16 (once per CTA) ----
    for (int i = t; i < 256 * 144; i += 512) {
        int n = i / 144, k = i - n * 144;
        int gate = (n >> 4) & 3;
        int j = ((n >> 6) << 4) + (n & 15);
        float x = 0.f;
        if (gate == 0) {
            if (k < 66) x = wih[j * 130 + 64 + k];
            else if (k < 130) x = whh[j * 64 + (k - 66)];
        } else if (gate == 1) {
            if (k < 66) x = wih[(64 + j) * 130 + 64 + k];
            else if (k < 130) x = whh[(64 + j) * 64 + (k - 66)];
        } else if (gate == 2) {
            if (k < 66) x = wih[(128 + j) * 130 + 64 + k];
        } else {
            if (k >= 66 && k < 130) x = whh[(128 + j) * 64 + (k - 66)];
        }
        smh[(KB_B_OFF >> 1) + n * BSTR_H + k] = __float2half_rn(x);
    }
    // ---- zero A pad cols k=130..143 (constant across tiles) ----
    for (int i = t; i < 128 * 16; i += 512) {
        int row = i >> 4, kk = 130 + (i & 15);
        if (kk < 144) smh[(KB_A_OFF >> 1) + row * 152 + kk] = __float2half_rn(0.f);
    }
    // ---- biases (fp32 epilogue, stress folded via g_gic) ----
    if (t < 64) {
        smf[KB_BI_F + t]       = g_gic[dir][t]       + bhh[t];        // r
        smf[KB_BI_F + 64 + t]  = g_gic[dir][64 + t]  + bhh[64 + t];   // z
        smf[KB_BI_F + 128 + t] = g_gic[dir][128 + t];                 // i_n
        smf[KB_BI_F + 192 + t] = bhh[128 + t];                        // h_n
    }
    __syncthreads();

    const float sc = 0.001f * g_stress;
    const int lane = t & 31, wid = t >> 5;
    const int rowg = wid >> 2;            // 0..3 : rows rowg*32..+31
    const int colg = wid & 3;             // 0..3 : j colg*16..+15 (64 n-cols)
    const float lam = 0.7f, oml = 0.3f;
    const int nblk = gridDim.x >> 1;

    // ldmatrix per-lane addressing
    const int lr = lane & 7, sel = lane >> 3;
    // A: sel0:(m+0,k0) sel1:(m+8,k0) sel2:(m+0,k0+8) sel3:(m+8,k0+8)
    const int a_row_l = ((sel & 1) << 3) + lr;
    const int a_kadd  = (sel >> 1) << 3;
    uint32_t addrA0 = smem_base + KB_A_OFF + (rowg * 32 + 0  + a_row_l) * ASTR_B + a_kadd * 2;
    uint32_t addrA1 = smem_base + KB_A_OFF + (rowg * 32 + 16 + a_row_l) * ASTR_B + a_kadd * 2;
    // B: sel0:(n+0,k0) sel1:(n+0,k0+8) sel2:(n+8,k0) sel3:(n+8,k0+8)
    const int b_n_l  = ((sel >> 1) << 3) + lr;
    const int b_kadd = (sel & 1) << 3;
    uint32_t addrB0 = smem_base + KB_B_OFF + (colg * 64 + b_n_l) * BSTR_B + b_kadd * 2;

    for (int tile = blockIdx.x >> 1; tile < ntiles; tile += nblk) {
        __syncthreads();
        const int row0 = tile * 128;

        // ---- stage A: e (k 0..63) + e_theta out (dir 0) ----
        {
            const float4* e4 = (const float4*)(g_e + (size_t)row0 * DIMV);
            float4* o4 = (float4*)(eout + (size_t)row0 * DIMV);
            for (int i = t; i < 2048; i += 512) {
                int row = i >> 4, q = i & 15;
                float4 v = e4[i];
                __half* dst = smh + (KB_A_OFF >> 1) + row * 152 + q * 4;
                *(__half2*)(dst)     = __floats2half2_rn(v.x, v.y);
                *(__half2*)(dst + 2) = __floats2half2_rn(v.z, v.w);
                if (dir == 0) {
                    float4 w = v;
                    w.x += sc; w.y += sc; w.z += sc; w.w += sc;
                    o4[i] = w;
                }
            }
        }
        // ---- stage h_prev: fp16 A cols 66..129 + fp32 copy ----
        {
            const float4* h4 = (const float4*)(hp + (size_t)row0 * DIMV);
            for (int i = t; i < 2048; i += 512) {
                int row = i >> 4, q = i & 15;
                float4 v = h4[i];
                *(float4*)(smf + KB_HB_F + row * 68 + q * 4) = v;
                __half* dst = smh + (KB_A_OFF >> 1) + row * 152 + 66 + q * 4;
                *(__half2*)(dst)     = __floats2half2_rn(v.x, v.y);
                *(__half2*)(dst + 2) = __floats2half2_rn(v.z, v.w);
            }
        }
        // ---- res/om k=64,65 ----
        if (t < 128) {
            *(__half2*)(smh + (KB_A_OFF >> 1) + t * 152 + 64) =
                __floats2half2_rn(res_in[row0 + t], om_in[row0 + t]);
        }
        __syncthreads();

        // ---- mma mainloop: 9 k-steps of 16 ----
        float acc[2][8][4];
        #pragma unroll
        for (int mb = 0; mb < 2; mb++)
            #pragma unroll
            for (int nb = 0; nb < 8; nb++)
                #pragma unroll
                for (int e = 0; e < 4; e++) acc[mb][nb][e] = 0.f;

        #pragma unroll 1
        for (int s = 0; s < 9; s++) {
            uint32_t a0[4], a1[4];
            ldmatrix_x4(a0[0], a0[1], a0[2], a0[3], addrA0 + s * 32);
            ldmatrix_x4(a1[0], a1[1], a1[2], a1[3], addrA1 + s * 32);
            #pragma unroll
            for (int p = 0; p < 4; p++) {
                uint32_t b[4];
                ldmatrix_x4(b[0], b[1], b[2], b[3], addrB0 + p * (16 * BSTR_B) + s * 32);
                mma_f16(acc[0][2*p],   a0[0], a0[1], a0[2], a0[3], b[0], b[1]);
                mma_f16(acc[0][2*p+1], a0[0], a0[1], a0[2], a0[3], b[2], b[3]);
                mma_f16(acc[1][2*p],   a1[0], a1[1], a1[2], a1[3], b[0], b[1]);
                mma_f16(acc[1][2*p+1], a1[0], a1[1], a1[2], a1[3], b[2], b[3]);
            }
        }

        // ---- epilogue: gates -> h (each (row,j) owned by one lane) ----
        const int e2 = lane & 3, rin = lane >> 2;
        #pragma unroll
        for (int hi = 0; hi < 2; hi++) {
            #pragma unroll
            for (int e = 0; e < 2; e++) {
                const int jl = hi * 8 + 2 * e2 + e;
                const int j = colg * 16 + jl;
                const float bR  = smf[KB_BI_F + j];
                const float bZ  = smf[KB_BI_F + 64 + j];
                const float bNx = smf[KB_BI_F + 128 + j];
                const float bNh = smf[KB_BI_F + 192 + j];
                #pragma unroll
                for (int mb = 0; mb < 2; mb++) {
                    #pragma unroll
                    for (int rh = 0; rh < 2; rh++) {
                        const int row = rowg * 32 + mb * 16 + rh * 8 + rin;
                        const int ci = rh * 2 + e;
                        float vR = acc[mb][0 + hi][ci] + bR;
                        float vZ = acc[mb][2 + hi][ci] + bZ;
                        float vN = acc[mb][4 + hi][ci] + bNx;
                        float vH = acc[mb][6 + hi][ci] + bNh;
                        float rg = 1.0f / (1.0f + expf(-vR));
                        float zg = 1.0f / (1.0f + expf(-vZ));
                        float ng = tanhf(fmaf(rg, vH, vN));
                        float hpv = smf[KB_HB_F + row * 68 + j];
                        smf[KB_HB_F + row * 68 + j] = fmaf(zg, hpv - ng, ng);
                    }
                }
            }
        }
        __syncthreads();

        // ---- coalesced write-out ----
        for (int i = t; i < 2048; i += 512) {
            int row = i >> 4, q = i & 15;
            float4 hv = *(const float4*)(smf + KB_HB_F + row * 68 + q * 4);
            const size_t ob = (size_t)(row0 + row) * DIMV + q * 4;
            *(float4*)(ho + ob) = hv;
            if (dir == 0) {
                float4 th = *(const float4*)(theta + ob);
                float4 tn;
                tn.x = fmaf(lam, hv.x, oml * th.x); tn.y = fmaf(lam, hv.y, oml * th.y);
                tn.z = fmaf(lam, hv.z, oml * th.z); tn.w = fmaf(lam, hv.w, oml * th.w);
                *(float4*)(thout + ob) = tn;
            }
        }
    }
}

// ================= launch =================
extern "C" void kernel_launch(void* const* d_in, const int* in_sizes, int n_in,
                              void* d_out, int out_size)
{
    const float* theta     = (const float*)d_in[0];
    const float* context   = (const float*)d_in[1];
    const float* h_prev    = (const float*)d_in[2];
    const float* memory    = (const float*)d_in[3];
    const float* tw        = (const float*)d_in[4];
    const float* ipw       = (const float*)d_in[5];
    const float* ipb       = (const float*)d_in[6];
    const float* outw      = (const float*)d_in[7];
    const float* outb      = (const float*)d_in[8];
    const float* emo_w1    = (const float*)d_in[9];
    const float* emo_b1    = (const float*)d_in[10];
    const float* emo_w2    = (const float*)d_in[11];
    const float* emo_b2    = (const float*)d_in[12];
    const float* prime_emb = (const float*)d_in[13];
    const float* ctx_w     = (const float*)d_in[14];
    const float* ctx_b     = (const float*)d_in[15];
    const float* ideal_w   = (const float*)d_in[16];
    const float* ideal_b   = (const float*)d_in[17];
    const float* wih_f     = (const float*)d_in[18];
    const float* whh_f     = (const float*)d_in[19];
    const float* bih_f     = (const float*)d_in[20];
    const float* bhh_f     = (const float*)d_in[21];
    const float* wih_r     = (const float*)d_in[22];
    const float* whh_r     = (const float*)d_in[23];
    const float* bih_r     = (const float*)d_in[24];
    const float* bhh_r     = (const float*)d_in[25];
    const float* freq_w    = (const float*)d_in[26];
    const float* freq_b    = (const float*)d_in[27];
    const float* prev_id   = (const float*)d_in[28];

    const int B = in_sizes[0] / DIMV;
    const int ntiles = B / 128;

    float* out = (float*)d_out;
    float* o_thn = out;
    float* o_h   = out + (size_t)B * DIMV;
    float* o_e   = out + (size_t)3 * B * DIMV;
    float* o_res = out + (size_t)4 * B * DIMV;
    float* o_om  = o_res + B;
    float* o_pw  = o_om + B;

    cudaFuncSetAttribute((const void*)kA2, cudaFuncAttributeMaxDynamicSharedMemorySize, SMEM_A2);
    cudaFuncSetAttribute((const void*)kB,  cudaFuncAttributeMaxDynamicSharedMemorySize, SMEM_KB);

    kC0<<<NPR, CTXD>>>(ideal_w, ctx_w, ctx_b, ideal_b);
    kA2<<<GRID_A, 512, SMEM_A2>>>(theta, context, emo_w1, emo_b1, emo_w2, emo_b2,
                                  prime_emb, ideal_w, prev_id,
                                  freq_w, freq_b, o_res, o_om, o_pw, ntiles);
    kC<<<1, 192>>>(tw, memory, ipw, ipb, outw, outb, wih_f, bih_f, wih_r, bih_r);
    kB<<<296, 512, SMEM_KB>>>(wih_f, whh_f, bhh_f, wih_r, whh_r, bhh_r,
                              h_prev, theta, o_res, o_om,
                              o_h, o_thn, o_e, ntiles, B);
}